// round 15
// baseline (speedup 1.0000x reference)
#include <cuda_runtime.h>
#include <cuda_fp16.h>
#include <cstdint>

#define LL 512
#define IN_DIM 256
#define DM 32      // dim_msa (contraction dims c and d)
#define PD 64      // pairwise dim
#define IPB 4      // i's per CTA in k_mma

// ---------------------------------------------------------------------------
// Global scratch. fp16 fragment layouts (single-term):
//   g_Af[ ((mt*2+ks)*32 + lane)*4 + reg ]            mt=j>>4 (32), ks=c>>4 (2)
//   g_Bf[ i*1024 + (nt*32 + lane)*4 + ks*2 + reg ]   nt=p>>3 (8), 16B/(nt,lane)
// ---------------------------------------------------------------------------
__device__ __align__(16) unsigned g_Af[8192];
__device__ __align__(16) unsigned g_Bf[512 * 1024];
__device__ float g_xT[DM * LL];          // x transposed: [d][i]

__device__ __forceinline__ unsigned pack_h2(float a, float b) {
    __half2 t = __floats2half2_rn(a, b);
    return *reinterpret_cast<unsigned*>(&t);
}

// ---------------------------------------------------------------------------
// Kernel A: x = seq @ W1^T + b1; emits g_xT + fp16 A-fragments.  [R13, passing]
// ---------------------------------------------------------------------------
#define W1PAD 260
__global__ void __launch_bounds__(128) k_proj1(const float* __restrict__ seq,
                                               const float* __restrict__ W1,
                                               const float* __restrict__ b1) {
    __shared__ __align__(16) float W1s[DM][W1PAD];
    __shared__ __align__(16) float seqs[4][IN_DIM];
    __shared__ __align__(16) float red[4][4][32];
    const int tid = threadIdx.x;
    const int i0 = blockIdx.x * 4;

    #pragma unroll
    for (int t = 0; t < 16; ++t) {
        int idx4 = t * 128 + tid;
        int d = idx4 >> 6, k4 = idx4 & 63;
        *(float4*)&W1s[d][k4 * 4] = ((const float4*)W1)[idx4];
    }
    #pragma unroll
    for (int t = 0; t < 2; ++t) {
        int idx4 = t * 128 + tid;
        int r = idx4 >> 6, k4 = idx4 & 63;
        *(float4*)&seqs[r][k4 * 4] = ((const float4*)seq)[(i0 + r) * 64 + k4];
    }
    __syncthreads();

    const int d  = tid & 31;
    const int kc = tid >> 5;
    float acc[4][4];
    #pragma unroll
    for (int r = 0; r < 4; ++r)
        #pragma unroll
        for (int e = 0; e < 4; ++e) acc[r][e] = 0.f;

    #pragma unroll
    for (int i4 = 0; i4 < 16; ++i4) {
        float4 wv = *(const float4*)&W1s[d][kc * 64 + i4 * 4];
        #pragma unroll
        for (int r = 0; r < 4; ++r) {
            float4 s = *(const float4*)&seqs[r][kc * 64 + i4 * 4];
            acc[r][0] = fmaf(s.x, wv.x, acc[r][0]);
            acc[r][1] = fmaf(s.y, wv.y, acc[r][1]);
            acc[r][2] = fmaf(s.z, wv.z, acc[r][2]);
            acc[r][3] = fmaf(s.w, wv.w, acc[r][3]);
        }
    }
    #pragma unroll
    for (int r = 0; r < 4; ++r)
        red[r][kc][d] = (acc[r][0] + acc[r][1]) + (acc[r][2] + acc[r][3]);
    __syncthreads();

    const int rr = tid >> 5, dd = tid & 31;
    float a = (red[rr][0][dd] + red[rr][1][dd]) +
              (red[rr][2][dd] + red[rr][3][dd]) + b1[dd];

    const int j = i0 + rr;
    g_xT[dd * LL + j] = a;

    float pv = __shfl_xor_sync(0xffffffffu, a, 1);
    if (!(dd & 1)) {
        const int mt = j >> 4, jr = j & 15;
        const int ks = dd >> 4, kcx = dd & 15;
        const int lane = (jr & 7) * 4 + ((kcx >> 1) & 3);
        const int reg  = (jr >> 3) | ((kcx >> 3) << 1);
        const int idx  = ((mt * 2 + ks) * 32 + lane) * 4 + reg;
        g_Af[idx] = pack_h2(a, pv);
    }
}

// ---------------------------------------------------------------------------
// Kernel B: T = x @ W2-slice; emits fp16 B-fragments only.  [R13, passing]
// ---------------------------------------------------------------------------
__global__ void __launch_bounds__(256) k_proj2(const float* __restrict__ W2) {
    __shared__ __align__(16) float ws[DM][256];
    __shared__ __align__(16) float xs[DM][32];
    const int tid = threadIdx.x;
    const int cp0 = blockIdx.x * 256;
    const int i0  = blockIdx.y * 32;

    #pragma unroll
    for (int t = 0; t < 32; ++t) {
        int idx = t * 256 + tid;
        int cpl = idx >> 5, k = idx & 31;
        int cp = cp0 + cpl;
        ws[k][cpl] = W2[(cp & 63) * 1024 + (cp >> 6) * 32 + k];
    }
    #pragma unroll
    for (int t = 0; t < 4; ++t) {
        int idx = t * 256 + tid;
        int k = idx >> 5, il = idx & 31;
        xs[k][il] = g_xT[k * LL + i0 + il];
    }
    __syncthreads();

    const int cg = tid & 31;
    const int ig = tid >> 5;
    float acc[4][8];
    #pragma unroll
    for (int a = 0; a < 4; ++a)
        #pragma unroll
        for (int b = 0; b < 8; ++b) acc[a][b] = 0.f;

    #pragma unroll 4
    for (int k = 0; k < DM; ++k) {
        float4 xv = *(const float4*)&xs[k][ig * 4];
        float4 wa = *(const float4*)&ws[k][cg * 8];
        float4 wb = *(const float4*)&ws[k][cg * 8 + 4];
        float xr[4] = {xv.x, xv.y, xv.z, xv.w};
        float wv[8] = {wa.x, wa.y, wa.z, wa.w, wb.x, wb.y, wb.z, wb.w};
        #pragma unroll
        for (int a = 0; a < 4; ++a)
            #pragma unroll
            for (int b = 0; b < 8; ++b)
                acc[a][b] = fmaf(xr[a], wv[b], acc[a][b]);
    }

    const int cbase = blockIdx.x * 4 + (cg >> 3);
    const bool even = ((cg >> 3) & 1) == 0;
    const int nt = cg & 7;
    #pragma unroll
    for (int a = 0; a < 4; ++a) {
        const int i = i0 + ig * 4 + a;
        unsigned* bf = g_Bf + i * 1024;
        #pragma unroll
        for (int b = 0; b < 8; ++b) {
            float v  = acc[a][b];
            float pv = __shfl_xor_sync(0xffffffffu, v, 8);
            if (even) {
                const int ks = cbase >> 4, kc = cbase & 15;
                const int lanef = b * 4 + ((kc >> 1) & 3);
                const int reg   = kc >> 3;
                const int bidx  = (nt * 32 + lanef) * 4 + ks * 2 + reg;
                bf[bidx] = pack_h2(v, pv);
            }
        }
    }
}

// ---------------------------------------------------------------------------
// Kernel C (barrier-free fp16 HMMA): out[i][j][p] = b2[p] + sum_c ...
// grid (4 jt, 128 ib), block 256 (8 warps, each 16 j x 64 p), 3 CTAs/SM.
// No smem, no syncs: B-frags via __ldg (L1-hot), bias pre-loaded into acc.
// ---------------------------------------------------------------------------
#define MMA_F16(C, A, B)                                                       \
    asm volatile("mma.sync.aligned.m16n8k16.row.col.f32.f16.f16.f32 "          \
                 "{%0,%1,%2,%3}, {%4,%5,%6,%7}, {%8,%9}, {%0,%1,%2,%3};"       \
                 : "+f"((C)[0]), "+f"((C)[1]), "+f"((C)[2]), "+f"((C)[3])      \
                 : "r"((A).x), "r"((A).y), "r"((A).z), "r"((A).w),             \
                   "r"((B).x), "r"((B).y))

__global__ void __launch_bounds__(256, 3) k_mma(const float* __restrict__ b2,
                                                float* __restrict__ out) {
    const int tid = threadIdx.x;
    const int w = tid >> 5, l = tid & 31;
    const int gid = l >> 2, q = l & 3;
    const int jt = blockIdx.x;             // 0..3, 128 j each
    const int ibase = blockIdx.y * IPB;
    const int mt = jt * 8 + w;             // one 16-j tile per warp

    // A fragments (i-independent): [ks]
    uint4 Af[2];
    #pragma unroll
    for (int ks = 0; ks < 2; ++ks)
        Af[ks] = *(const uint4*)(g_Af + ((mt * 2 + ks) * 32 + l) * 4);

    // bias per lane (acc initializer)
    float2 bb[8];
    #pragma unroll
    for (int n = 0; n < 8; ++n)
        bb[n] = __ldg((const float2*)(b2 + n * 8 + 2 * q));

    #pragma unroll
    for (int t = 0; t < IPB; ++t) {
        const int i = ibase + t;
        const uint4* __restrict__ bsrc = (const uint4*)(g_Bf + i * 1024);

        float acc[8][4];
        #pragma unroll
        for (int n = 0; n < 8; ++n) {
            acc[n][0] = bb[n].x; acc[n][1] = bb[n].y;
            acc[n][2] = bb[n].x; acc[n][3] = bb[n].y;
        }

        #pragma unroll
        for (int n = 0; n < 8; ++n) {
            uint4 B = __ldg(bsrc + (n * 32 + l));
            uint2 B0 = make_uint2(B.x, B.y);   // ks=0
            uint2 B1 = make_uint2(B.z, B.w);   // ks=1
            MMA_F16(acc[n], Af[0], B0);
            MMA_F16(acc[n], Af[1], B1);
        }

        float* rowbase = out + ((size_t)i * LL + jt * 128 + w * 16) * PD;
        #pragma unroll
        for (int n = 0; n < 8; ++n) {
            float* d0 = rowbase + gid * PD + n * 8 + 2 * q;
            *(float2*)d0            = make_float2(acc[n][0], acc[n][1]);
            *(float2*)(d0 + 8 * PD) = make_float2(acc[n][2], acc[n][3]);
        }
    }
}

// ---------------------------------------------------------------------------
extern "C" void kernel_launch(void* const* d_in, const int* in_sizes, int n_in,
                              void* d_out, int out_size) {
    const float* seq = (const float*)d_in[0];
    const float* W1  = (const float*)d_in[1];
    const float* b1  = (const float*)d_in[2];
    const float* W2  = (const float*)d_in[3];
    const float* b2  = (const float*)d_in[4];
    float* out = (float*)d_out;

    k_proj1<<<128, 128>>>(seq, W1, b1);
    k_proj2<<<dim3(8, 16), 256>>>(W2);
    k_mma<<<dim3(4, LL / IPB), 256>>>(b2, out);
}

// round 16
// speedup vs baseline: 1.1758x; 1.1758x over previous
#include <cuda_runtime.h>
#include <cuda_fp16.h>
#include <cstdint>

#define LL 512
#define IN_DIM 256
#define DM 32      // dim_msa (contraction dims c and d)
#define PD 64      // pairwise dim
#define IPB 4      // i's per CTA in k_mma

// ---------------------------------------------------------------------------
// Global scratch. fp16 fragment layouts (single-term):
//   g_Af[ ((mt*2+ks)*32 + lane)*4 + reg ]            mt=j>>4 (32), ks=c>>4 (2)
//   g_Bf[ i*1024 + (nt*32 + lane)*4 + ks*2 + reg ]   nt=p>>3 (8), 16B/(nt,lane)
// ---------------------------------------------------------------------------
__device__ __align__(16) unsigned g_Af[8192];
__device__ __align__(16) unsigned g_Bf[512 * 1024];
__device__ float g_xT[DM * LL];          // x transposed: [d][i]

__device__ __forceinline__ unsigned pack_h2(float a, float b) {
    __half2 t = __floats2half2_rn(a, b);
    return *reinterpret_cast<unsigned*>(&t);
}
__device__ __forceinline__ uint32_t smem_u32(const void* p) {
    uint32_t a;
    asm("{ .reg .u64 t; cvta.to.shared.u64 t, %1; cvt.u32.u64 %0, t; }"
        : "=r"(a) : "l"(p));
    return a;
}
__device__ __forceinline__ void cp_async16(uint32_t dst, const void* src) {
    asm volatile("cp.async.cg.shared.global [%0], [%1], 16;"
                 :: "r"(dst), "l"(src) : "memory");
}
__device__ __forceinline__ void cp_commit() {
    asm volatile("cp.async.commit_group;" ::: "memory");
}
template <int N>
__device__ __forceinline__ void cp_wait() {
    asm volatile("cp.async.wait_group %0;" :: "n"(N) : "memory");
}

// ---------------------------------------------------------------------------
// Kernel A: x = seq @ W1^T + b1; emits g_xT + fp16 A-fragments.  [R13, passing]
// ---------------------------------------------------------------------------
#define W1PAD 260
__global__ void __launch_bounds__(128) k_proj1(const float* __restrict__ seq,
                                               const float* __restrict__ W1,
                                               const float* __restrict__ b1) {
    __shared__ __align__(16) float W1s[DM][W1PAD];
    __shared__ __align__(16) float seqs[4][IN_DIM];
    __shared__ __align__(16) float red[4][4][32];
    const int tid = threadIdx.x;
    const int i0 = blockIdx.x * 4;

    #pragma unroll
    for (int t = 0; t < 16; ++t) {
        int idx4 = t * 128 + tid;
        int d = idx4 >> 6, k4 = idx4 & 63;
        *(float4*)&W1s[d][k4 * 4] = ((const float4*)W1)[idx4];
    }
    #pragma unroll
    for (int t = 0; t < 2; ++t) {
        int idx4 = t * 128 + tid;
        int r = idx4 >> 6, k4 = idx4 & 63;
        *(float4*)&seqs[r][k4 * 4] = ((const float4*)seq)[(i0 + r) * 64 + k4];
    }
    __syncthreads();

    const int d  = tid & 31;
    const int kc = tid >> 5;
    float acc[4][4];
    #pragma unroll
    for (int r = 0; r < 4; ++r)
        #pragma unroll
        for (int e = 0; e < 4; ++e) acc[r][e] = 0.f;

    #pragma unroll
    for (int i4 = 0; i4 < 16; ++i4) {
        float4 wv = *(const float4*)&W1s[d][kc * 64 + i4 * 4];
        #pragma unroll
        for (int r = 0; r < 4; ++r) {
            float4 s = *(const float4*)&seqs[r][kc * 64 + i4 * 4];
            acc[r][0] = fmaf(s.x, wv.x, acc[r][0]);
            acc[r][1] = fmaf(s.y, wv.y, acc[r][1]);
            acc[r][2] = fmaf(s.z, wv.z, acc[r][2]);
            acc[r][3] = fmaf(s.w, wv.w, acc[r][3]);
        }
    }
    #pragma unroll
    for (int r = 0; r < 4; ++r)
        red[r][kc][d] = (acc[r][0] + acc[r][1]) + (acc[r][2] + acc[r][3]);
    __syncthreads();

    const int rr = tid >> 5, dd = tid & 31;
    float a = (red[rr][0][dd] + red[rr][1][dd]) +
              (red[rr][2][dd] + red[rr][3][dd]) + b1[dd];

    const int j = i0 + rr;
    g_xT[dd * LL + j] = a;

    float pv = __shfl_xor_sync(0xffffffffu, a, 1);
    if (!(dd & 1)) {
        const int mt = j >> 4, jr = j & 15;
        const int ks = dd >> 4, kcx = dd & 15;
        const int lane = (jr & 7) * 4 + ((kcx >> 1) & 3);
        const int reg  = (jr >> 3) | ((kcx >> 3) << 1);
        const int idx  = ((mt * 2 + ks) * 32 + lane) * 4 + reg;
        g_Af[idx] = pack_h2(a, pv);
    }
}

// ---------------------------------------------------------------------------
// Kernel B: T = x @ W2-slice; emits fp16 B-fragments only.  [R13, passing]
// ---------------------------------------------------------------------------
__global__ void __launch_bounds__(256) k_proj2(const float* __restrict__ W2) {
    __shared__ __align__(16) float ws[DM][256];
    __shared__ __align__(16) float xs[DM][32];
    const int tid = threadIdx.x;
    const int cp0 = blockIdx.x * 256;
    const int i0  = blockIdx.y * 32;

    #pragma unroll
    for (int t = 0; t < 32; ++t) {
        int idx = t * 256 + tid;
        int cpl = idx >> 5, k = idx & 31;
        int cp = cp0 + cpl;
        ws[k][cpl] = W2[(cp & 63) * 1024 + (cp >> 6) * 32 + k];
    }
    #pragma unroll
    for (int t = 0; t < 4; ++t) {
        int idx = t * 256 + tid;
        int k = idx >> 5, il = idx & 31;
        xs[k][il] = g_xT[k * LL + i0 + il];
    }
    __syncthreads();

    const int cg = tid & 31;
    const int ig = tid >> 5;
    float acc[4][8];
    #pragma unroll
    for (int a = 0; a < 4; ++a)
        #pragma unroll
        for (int b = 0; b < 8; ++b) acc[a][b] = 0.f;

    #pragma unroll 4
    for (int k = 0; k < DM; ++k) {
        float4 xv = *(const float4*)&xs[k][ig * 4];
        float4 wa = *(const float4*)&ws[k][cg * 8];
        float4 wb = *(const float4*)&ws[k][cg * 8 + 4];
        float xr[4] = {xv.x, xv.y, xv.z, xv.w};
        float wv[8] = {wa.x, wa.y, wa.z, wa.w, wb.x, wb.y, wb.z, wb.w};
        #pragma unroll
        for (int a = 0; a < 4; ++a)
            #pragma unroll
            for (int b = 0; b < 8; ++b)
                acc[a][b] = fmaf(xr[a], wv[b], acc[a][b]);
    }

    const int cbase = blockIdx.x * 4 + (cg >> 3);
    const bool even = ((cg >> 3) & 1) == 0;
    const int nt = cg & 7;
    #pragma unroll
    for (int a = 0; a < 4; ++a) {
        const int i = i0 + ig * 4 + a;
        unsigned* bf = g_Bf + i * 1024;
        #pragma unroll
        for (int b = 0; b < 8; ++b) {
            float v  = acc[a][b];
            float pv = __shfl_xor_sync(0xffffffffu, v, 8);
            if (even) {
                const int ks = cbase >> 4, kc = cbase & 15;
                const int lanef = b * 4 + ((kc >> 1) & 3);
                const int reg   = kc >> 3;
                const int bidx  = (nt * 32 + lanef) * 4 + ks * 2 + reg;
                bf[bidx] = pack_h2(v, pv);
            }
        }
    }
}

// ---------------------------------------------------------------------------
// Kernel C (fp16 HMMA, deep prefetch): out[i][j][p] = b2[p] + sum_c ...
// grid (2 jt, 128 ib), block 256 (8 warps x 32j x 64p), 2 CTAs/SM.
// All IPB stages prefetched upfront into 4 independent buffers; one sync per
// stage (no buffer reuse). Bias pre-loaded as accumulator initializer.
// ---------------------------------------------------------------------------
#define MMA_F16(C, A, B)                                                       \
    asm volatile("mma.sync.aligned.m16n8k16.row.col.f32.f16.f16.f32 "          \
                 "{%0,%1,%2,%3}, {%4,%5,%6,%7}, {%8,%9}, {%0,%1,%2,%3};"       \
                 : "+f"((C)[0]), "+f"((C)[1]), "+f"((C)[2]), "+f"((C)[3])      \
                 : "r"((A).x), "r"((A).y), "r"((A).z), "r"((A).w),             \
                   "r"((B).x), "r"((B).y))

__global__ void __launch_bounds__(256, 2) k_mma(const float* __restrict__ b2,
                                                float* __restrict__ out) {
    __shared__ __align__(16) unsigned smBf[IPB][1024];   // 16 KB, 1 buf/stage

    const int tid = threadIdx.x;
    const int w = tid >> 5, l = tid & 31;
    const int gid = l >> 2, q = l & 3;
    const int jt = blockIdx.x;
    const int ibase = blockIdx.y * IPB;

    const uint32_t smb = smem_u32(&smBf[0][0]);

    // issue ALL stage loads upfront (4 groups of 4 KB)
    #pragma unroll
    for (int t = 0; t < IPB; ++t) {
        cp_async16(smb + t * 4096 + tid * 16,
                   (const uint4*)(g_Bf + (ibase + t) * 1024) + tid);
        cp_commit();
    }

    // A fragments once per CTA (i-independent): [ks][m]
    uint4 Af[2][2];
    #pragma unroll
    for (int ks = 0; ks < 2; ++ks)
        #pragma unroll
        for (int m = 0; m < 2; ++m) {
            const int mt  = jt * 16 + w * 2 + m;
            const int off = ((mt * 2 + ks) * 32 + l) * 4;
            Af[ks][m] = *(const uint4*)(g_Af + off);
        }

    // bias per lane (acc initializer)
    float2 bb[8];
    #pragma unroll
    for (int n = 0; n < 8; ++n)
        bb[n] = __ldg((const float2*)(b2 + n * 8 + 2 * q));

    #pragma unroll
    for (int t = 0; t < IPB; ++t) {
        switch (t) {                       // wait for stage t's group only
            case 0: cp_wait<IPB - 1>(); break;
            case 1: cp_wait<IPB - 2>(); break;
            case 2: cp_wait<IPB - 3>(); break;
            default: cp_wait<0>(); break;
        }
        __syncthreads();                   // single barrier per stage

        const unsigned* bf = &smBf[t][0];
        float* rowbase = out + ((size_t)(ibase + t) * LL + jt * 256 + w * 32) * PD;

        float acc[2][8][4];
        #pragma unroll
        for (int m = 0; m < 2; ++m)
            #pragma unroll
            for (int n = 0; n < 8; ++n) {
                acc[m][n][0] = bb[n].x; acc[m][n][1] = bb[n].y;
                acc[m][n][2] = bb[n].x; acc[m][n][3] = bb[n].y;
            }

        #pragma unroll
        for (int n = 0; n < 8; ++n) {
            uint4 B = *(const uint4*)(bf + (n * 32 + l) * 4);
            uint2 B0 = make_uint2(B.x, B.y);   // ks=0
            uint2 B1 = make_uint2(B.z, B.w);   // ks=1
            #pragma unroll
            for (int m = 0; m < 2; ++m) {
                MMA_F16(acc[m][n], Af[0][m], B0);
                MMA_F16(acc[m][n], Af[1][m], B1);
            }
        }

        #pragma unroll
        for (int m = 0; m < 2; ++m)
            #pragma unroll
            for (int n = 0; n < 8; ++n) {
                float* d0 = rowbase + (m * 16 + gid) * PD + n * 8 + 2 * q;
                *(float2*)d0            = make_float2(acc[m][n][0], acc[m][n][1]);
                *(float2*)(d0 + 8 * PD) = make_float2(acc[m][n][2], acc[m][n][3]);
            }
    }
}

// ---------------------------------------------------------------------------
extern "C" void kernel_launch(void* const* d_in, const int* in_sizes, int n_in,
                              void* d_out, int out_size) {
    const float* seq = (const float*)d_in[0];
    const float* W1  = (const float*)d_in[1];
    const float* b1  = (const float*)d_in[2];
    const float* W2  = (const float*)d_in[3];
    const float* b2  = (const float*)d_in[4];
    float* out = (float*)d_out;

    k_proj1<<<128, 128>>>(seq, W1, b1);
    k_proj2<<<dim3(8, 16), 256>>>(W2);
    k_mma<<<dim3(2, LL / IPB), 256>>>(b2, out);
}